// round 2
// baseline (speedup 1.0000x reference)
#include <cuda_runtime.h>
#include <cuda_bf16.h>
#include <cstdint>

#define B_ 128
#define S_ 512
#define I_ 128
#define H_ 128
#define M_ 8
#define KD_ 16
#define R_ 16
#define O_ 128

// output region offsets (floats), concatenated in reference return order
#define OFF_OUT   ((size_t)0)                 // [B,S,O]      8388608
#define OFF_HID   ((size_t)8388608)           // [S,B,M,H]   67108864
#define OFF_AIN   ((size_t)75497472)          // [S,B,M,H]   67108864
#define OFF_ACOMM ((size_t)142606336)         // [S,B,M,H]   67108864
#define OFF_ARIM  ((size_t)209715200)         // [S,B,M,M]    4194304

__device__ float g_P[(size_t)S_ * B_ * M_ * H_];   // 256 MB scratch: precomputed input_part(+biases)
__device__ float g_Weff[M_ * I_ * H_];             // W_in @ Wp^T per mechanism

// ---------------------------------------------------------------------------
// k_weff: Weff[m][i][o] = sum_h Win[m][i][h] * Wp[m][o][h]
// grid (2, 8), 256 threads
// ---------------------------------------------------------------------------
__global__ void k_weff(const float* __restrict__ Win, const float* __restrict__ Wp) {
    __shared__ float sA[64][36];
    __shared__ float sBt[32][132];
    int m = blockIdx.y;
    int i0 = blockIdx.x * 64;
    int tid = threadIdx.x;
    int ty = tid >> 5, tx = tid & 31;
    int w = tid >> 5, lane = tid & 31;

    float acc[8][4];
#pragma unroll
    for (int a = 0; a < 8; a++)
#pragma unroll
        for (int c = 0; c < 4; c++) acc[a][c] = 0.f;

    const float* A = Win + m * 16384;
    const float* Bm = Wp + m * 16384;

    for (int kc = 0; kc < 128; kc += 32) {
        // load A tile (rows=i, cols=h-chunk)
        {
            int row = tid >> 2, cs = (tid & 3) * 8;
            const float* ap = A + (i0 + row) * 128 + kc + cs;
            *(float4*)&sA[row][cs]     = *(const float4*)ap;
            *(float4*)&sA[row][cs + 4] = *(const float4*)(ap + 4);
        }
        // transpose-load B tile: sBt[hh][o]
        {
            int og = lane >> 3, ii0 = (lane & 7) * 4;
#pragma unroll
            for (int it = 0; it < 4; it++) {
                int o = (w << 4) + og + (it << 2);
                float4 v = *(const float4*)(Bm + o * 128 + kc + ii0);
                sBt[ii0 + 0][o] = v.x; sBt[ii0 + 1][o] = v.y;
                sBt[ii0 + 2][o] = v.z; sBt[ii0 + 3][o] = v.w;
            }
        }
        __syncthreads();
#pragma unroll 8
        for (int kk = 0; kk < 32; kk++) {
            float4 wv = *(float4*)&sBt[kk][tx * 4];
#pragma unroll
            for (int rr = 0; rr < 8; rr++) {
                float av = sA[ty * 8 + rr][kk];
                acc[rr][0] += av * wv.x; acc[rr][1] += av * wv.y;
                acc[rr][2] += av * wv.z; acc[rr][3] += av * wv.w;
            }
        }
        __syncthreads();
    }
    float* dst = g_Weff + m * 16384;
#pragma unroll
    for (int rr = 0; rr < 8; rr++) {
        float4 v = make_float4(acc[rr][0], acc[rr][1], acc[rr][2], acc[rr][3]);
        *(float4*)&dst[(i0 + ty * 8 + rr) * 128 + tx * 4] = v;
    }
}

// ---------------------------------------------------------------------------
// k_pre: for every (t,b) row: A_in[t,b,m,:] = x[b,t,:] @ Win[m]
//                             P[t,b,m,:]   = x[b,t,:] @ Weff[m] + bp[m]+cb[m]
// grid (1024, 8): 64 (t,b)-rows per block, m = blockIdx.y. 256 threads.
// ---------------------------------------------------------------------------
__global__ void k_pre(const float* __restrict__ x, const float* __restrict__ Win,
                      const float* __restrict__ bp, const float* __restrict__ cb,
                      float* __restrict__ ain) {
    __shared__ float sX[64][36];
    __shared__ float sW1[32][132];
    __shared__ float sW2[32][132];
    int m = blockIdx.y;
    int r0 = blockIdx.x * 64;           // global (t,b) row = t*128+b
    int t = r0 >> 7, b0 = r0 & 127;
    int tid = threadIdx.x;
    int ty = tid >> 5, tx = tid & 31;

    float acc1[8][4], acc2[8][4];
#pragma unroll
    for (int a = 0; a < 8; a++)
#pragma unroll
        for (int c = 0; c < 4; c++) { acc1[a][c] = 0.f; acc2[a][c] = 0.f; }

    const float* W1 = Win + m * 16384;
    const float* W2 = g_Weff + m * 16384;

    for (int kc = 0; kc < 128; kc += 32) {
        {
            int row = tid >> 2, cs = (tid & 3) * 8;
            const float* xp = x + ((size_t)(b0 + row) * 512 + t) * 128 + kc + cs;
            *(float4*)&sX[row][cs]     = *(const float4*)xp;
            *(float4*)&sX[row][cs + 4] = *(const float4*)(xp + 4);
        }
        {
            int i = tid >> 3, h0 = (tid & 7) * 16;
            const float* w1 = W1 + (kc + i) * 128 + h0;
            const float* w2 = W2 + (kc + i) * 128 + h0;
#pragma unroll
            for (int j = 0; j < 4; j++) {
                *(float4*)&sW1[i][h0 + 4 * j] = *(const float4*)(w1 + 4 * j);
                *(float4*)&sW2[i][h0 + 4 * j] = *(const float4*)(w2 + 4 * j);
            }
        }
        __syncthreads();
#pragma unroll 8
        for (int kk = 0; kk < 32; kk++) {
            float4 w1 = *(float4*)&sW1[kk][tx * 4];
            float4 w2 = *(float4*)&sW2[kk][tx * 4];
#pragma unroll
            for (int rr = 0; rr < 8; rr++) {
                float xv = sX[ty * 8 + rr][kk];
                acc1[rr][0] += xv * w1.x; acc1[rr][1] += xv * w1.y;
                acc1[rr][2] += xv * w1.z; acc1[rr][3] += xv * w1.w;
                acc2[rr][0] += xv * w2.x; acc2[rr][1] += xv * w2.y;
                acc2[rr][2] += xv * w2.z; acc2[rr][3] += xv * w2.w;
            }
        }
        __syncthreads();
    }
    float4 bi = *(const float4*)&bp[m * 128 + tx * 4];
    float4 ci = *(const float4*)&cb[m * 128 + tx * 4];
    float4 bias = make_float4(bi.x + ci.x, bi.y + ci.y, bi.z + ci.z, bi.w + ci.w);
#pragma unroll
    for (int rr = 0; rr < 8; rr++) {
        size_t gr = r0 + ty * 8 + rr;
        size_t base = (gr * 8 + m) * 128 + tx * 4;
        *(float4*)&ain[base] = make_float4(acc1[rr][0], acc1[rr][1], acc1[rr][2], acc1[rr][3]);
        *(float4*)&g_P[base] = make_float4(acc2[rr][0] + bias.x, acc2[rr][1] + bias.y,
                                           acc2[rr][2] + bias.z, acc2[rr][3] + bias.w);
    }
}

// ---------------------------------------------------------------------------
// k_rnn: persistent per-batch recurrence. 128 blocks (one per b), 256 threads.
// Weights resident in SMEM; P streamed with cp.async double buffer.
// ---------------------------------------------------------------------------
struct Smem3 {
    float U[M_][H_][R_];              // 64KB
    float V[M_][R_][H_];              // 64KB
    __nv_bfloat162 QK[M_][32][64];    // 64KB: cols 0..15 = W_K, 16..31 = W_Q, [m][col][h/2]
    float diag[M_][H_];
    float Hst[M_][H_];
    float Hin[M_][H_];
    float VcT[M_][H_];
    float P[2][M_ * H_];
    float KQ[M_][32];
    float Log[M_][M_];
    float Attn[M_][M_];
};

__device__ __forceinline__ void cp16(void* s, const void* g) {
    unsigned ds = (unsigned)__cvta_generic_to_shared(s);
    asm volatile("cp.async.cg.shared.global [%0], [%1], 16;" :: "r"(ds), "l"(g));
}

__global__ void k_rnn(const float* __restrict__ U, const float* __restrict__ V,
                      const float* __restrict__ WQ, const float* __restrict__ WK,
                      const float* __restrict__ WV,
                      float* __restrict__ hid, float* __restrict__ acomm,
                      float* __restrict__ arim) {
    extern __shared__ char raw[];
    Smem3& sm = *reinterpret_cast<Smem3*>(raw);
    int tid = threadIdx.x;
    int b = blockIdx.x;
    int w = tid >> 5, lane = tid & 31;

    // -------- init: load weights --------
    for (int i = tid * 4; i < M_ * H_ * R_; i += 256 * 4) {
        *(float4*)((float*)sm.U + i) = *(const float4*)(U + i);
        *(float4*)((float*)sm.V + i) = *(const float4*)(V + i);
    }
    {
        int m = tid >> 5, c = tid & 31;
        const float* src = (c < 16) ? (WK + m * H_ * KD_ + c)
                                    : (WQ + m * H_ * KD_ + (c - 16));
        for (int hp = 0; hp < 64; hp++) {
            float a0 = src[(2 * hp) * KD_];
            float a1 = src[(2 * hp + 1) * KD_];
            sm.QK[m][c][hp] = __floats2bfloat162_rn(a0, a1);
        }
    }
    for (int e = tid; e < M_ * H_; e += 256) {
        int m = e >> 7, h = e & 127;
        sm.diag[m][h] = WV[((size_t)m * H_ + h) * H_ + h];
        sm.Hst[m][h] = 0.f;
    }
    const float* Pb = g_P + (size_t)b * 1024;
    cp16(&sm.P[0][tid * 4], Pb + tid * 4);
    asm volatile("cp.async.commit_group;");
    __syncthreads();

    const int m = w;  // warp <-> mechanism
    const int r = lane & 15, half = lane >> 4;

    for (int t = 0; t < S_; t++) {
        if (t + 1 < S_) {
            cp16(&sm.P[(t + 1) & 1][tid * 4],
                 Pb + (size_t)(t + 1) * (B_ * 1024) + tid * 4);
            asm volatile("cp.async.commit_group;");
            asm volatile("cp.async.wait_group 1;");
        } else {
            asm volatile("cp.async.wait_group 0;");
        }
        __syncthreads();

        // ---- phase A: rec = (H @ U) @ V ; Hin = tanh(P + rec) ; VcT = Hin*diag
        {
            const float* Uc = &sm.U[m][half * 64][r];
            const float* Hc = &sm.Hst[m][half * 64];
            float p0 = 0, p1 = 0, p2 = 0, p3 = 0;
#pragma unroll
            for (int hh = 0; hh < 64; hh += 4) {
                p0 += Hc[hh + 0] * Uc[(hh + 0) * 16];
                p1 += Hc[hh + 1] * Uc[(hh + 1) * 16];
                p2 += Hc[hh + 2] * Uc[(hh + 2) * 16];
                p3 += Hc[hh + 3] * Uc[(hh + 3) * 16];
            }
            float partial = (p0 + p1) + (p2 + p3);
            partial += __shfl_xor_sync(0xffffffffu, partial, 16);
            float4 acc = {0, 0, 0, 0};
#pragma unroll
            for (int rr = 0; rr < 16; rr++) {
                float tr = __shfl_sync(0xffffffffu, partial, rr);
                float4 v = *(const float4*)&sm.V[m][rr][lane * 4];
                acc.x += tr * v.x; acc.y += tr * v.y;
                acc.z += tr * v.z; acc.w += tr * v.w;
            }
            float4 pv = *(const float4*)&sm.P[t & 1][m * 128 + lane * 4];
            float4 hin;
            hin.x = tanhf(pv.x + acc.x);
            hin.y = tanhf(pv.y + acc.y);
            hin.z = tanhf(pv.z + acc.z);
            hin.w = tanhf(pv.w + acc.w);
            *(float4*)&sm.Hin[m][lane * 4] = hin;
            float4 dg = *(const float4*)&sm.diag[m][lane * 4];
            float4 vc = make_float4(hin.x * dg.x, hin.y * dg.y, hin.z * dg.z, hin.w * dg.w);
            *(float4*)&sm.VcT[m][lane * 4] = vc;
        }
        __syncthreads();

        // ---- phase B: K/Q projections (bf16 weights)
        {
            int c = lane;
            const __nv_bfloat162* qk = &sm.QK[m][c][0];
            const float2* hb = (const float2*)&sm.Hin[m][0];
            float q0 = 0, q1 = 0;
#pragma unroll 8
            for (int hp = 0; hp < 64; hp += 2) {
                float2 h0 = hb[hp], h1 = hb[hp + 1];
                float2 w0 = __bfloat1622float2(qk[hp]);
                float2 w1 = __bfloat1622float2(qk[hp + 1]);
                q0 += h0.x * w0.x + h0.y * w0.y;
                q1 += h1.x * w1.x + h1.y * w1.y;
            }
            sm.KQ[m][c] = q0 + q1;
        }
        __syncthreads();

        // ---- phase C1: logits + softmax
        if (tid < 64) {
            int mq = tid >> 3, n = tid & 7;
            float l = 0;
#pragma unroll
            for (int k = 0; k < 16; k++) l += sm.KQ[mq][16 + k] * sm.KQ[n][k];
            sm.Log[mq][n] = l * 0.25f;
        }
        __syncthreads();
        if (tid < 8) {
            float mx = -1e30f;
#pragma unroll
            for (int n = 0; n < 8; n++) mx = fmaxf(mx, sm.Log[tid][n]);
            float e[8], s = 0;
#pragma unroll
            for (int n = 0; n < 8; n++) { e[n] = __expf(sm.Log[tid][n] - mx); s += e[n]; }
            float inv = 1.0f / s;
#pragma unroll
            for (int n = 0; n < 8; n++) sm.Attn[tid][n] = e[n] * inv;
        }
        __syncthreads();

        // ---- phase C2: A_comm[n][h] = sum_m attn[m][n]*VcT[m][h]; update + write
        {
            int n = w;
            float4 ac = {0, 0, 0, 0};
#pragma unroll
            for (int mm = 0; mm < 8; mm++) {
                float a = sm.Attn[mm][n];
                float4 vc = *(const float4*)&sm.VcT[mm][lane * 4];
                ac.x += a * vc.x; ac.y += a * vc.y;
                ac.z += a * vc.z; ac.w += a * vc.w;
            }
            float4 hi = *(const float4*)&sm.Hin[n][lane * 4];
            float4 hn = make_float4(hi.x + ac.x, hi.y + ac.y, hi.z + ac.z, hi.w + ac.w);
            *(float4*)&sm.Hst[n][lane * 4] = hn;
            size_t base = (((size_t)t * B_ + b) * M_ + n) * H_ + lane * 4;
            *(float4*)&hid[base] = hn;
            *(float4*)&acomm[base] = ac;
            if (tid < 64)
                arim[((size_t)t * B_ + b) * 64 + tid] = sm.Attn[tid >> 3][tid & 7];
        }
        __syncthreads();
    }
}

// ---------------------------------------------------------------------------
// k_out: out[b,t,o] = hid[t,b,:,:] (flat 1024) @ Wo^T + bo. grid 1024, 256 thr.
// ---------------------------------------------------------------------------
__global__ void k_out(const float* __restrict__ hid, const float* __restrict__ Wo,
                      const float* __restrict__ bo, float* __restrict__ outp) {
    __shared__ float sA[64][36];
    __shared__ float sBt[32][132];
    int r0 = blockIdx.x * 64;
    int tid = threadIdx.x;
    int ty = tid >> 5, tx = tid & 31;
    int w = tid >> 5, lane = tid & 31;

    float acc[8][4];
#pragma unroll
    for (int a = 0; a < 8; a++)
#pragma unroll
        for (int c = 0; c < 4; c++) acc[a][c] = 0.f;

    for (int kc = 0; kc < 1024; kc += 32) {
        {
            int row = tid >> 2, cs = (tid & 3) * 8;
            const float* ap = hid + (size_t)(r0 + row) * 1024 + kc + cs;
            *(float4*)&sA[row][cs]     = *(const float4*)ap;
            *(float4*)&sA[row][cs + 4] = *(const float4*)(ap + 4);
        }
        {
            int og = lane >> 3, ii0 = (lane & 7) * 4;
#pragma unroll
            for (int it = 0; it < 4; it++) {
                int o = (w << 4) + og + (it << 2);
                float4 v = *(const float4*)(Wo + (size_t)o * 1024 + kc + ii0);
                sBt[ii0 + 0][o] = v.x; sBt[ii0 + 1][o] = v.y;
                sBt[ii0 + 2][o] = v.z; sBt[ii0 + 3][o] = v.w;
            }
        }
        __syncthreads();
#pragma unroll 8
        for (int kk = 0; kk < 32; kk++) {
            float4 wv = *(float4*)&sBt[kk][tx * 4];
#pragma unroll
            for (int rr = 0; rr < 8; rr++) {
                float av = sA[ty * 8 + rr][kk];
                acc[rr][0] += av * wv.x; acc[rr][1] += av * wv.y;
                acc[rr][2] += av * wv.z; acc[rr][3] += av * wv.w;
            }
        }
        __syncthreads();
    }
    float4 b4 = *(const float4*)&bo[tx * 4];
#pragma unroll
    for (int rr = 0; rr < 8; rr++) {
        int rg = r0 + ty * 8 + rr;
        int t = rg >> 7, b = rg & 127;
        float4 v = make_float4(acc[rr][0] + b4.x, acc[rr][1] + b4.y,
                               acc[rr][2] + b4.z, acc[rr][3] + b4.w);
        *(float4*)&outp[((size_t)b * 512 + t) * 128 + tx * 4] = v;
    }
}

// ---------------------------------------------------------------------------
extern "C" void kernel_launch(void* const* d_in, const int* in_sizes, int n_in,
                              void* d_out, int out_size) {
    const float* x    = (const float*)d_in[0];
    const float* Wp   = (const float*)d_in[1];
    const float* bp   = (const float*)d_in[2];
    const float* U    = (const float*)d_in[3];
    const float* V    = (const float*)d_in[4];
    const float* cb   = (const float*)d_in[5];
    const float* Win  = (const float*)d_in[6];
    const float* WQ   = (const float*)d_in[7];
    const float* WK   = (const float*)d_in[8];
    const float* WV   = (const float*)d_in[9];
    const float* Wo   = (const float*)d_in[10];
    const float* bo   = (const float*)d_in[11];

    float* out = (float*)d_out;
    float* outputs = out + OFF_OUT;
    float* hid     = out + OFF_HID;
    float* ain     = out + OFF_AIN;
    float* acomm   = out + OFF_ACOMM;
    float* arim    = out + OFF_ARIM;

    cudaFuncSetAttribute(k_rnn, cudaFuncAttributeMaxDynamicSharedMemorySize,
                         (int)sizeof(Smem3));

    k_weff<<<dim3(2, 8), 256>>>(Win, Wp);
    k_pre<<<dim3(1024, 8), 256>>>(x, Win, bp, cb, ain);
    k_rnn<<<128, 256, sizeof(Smem3)>>>(U, V, WQ, WK, WV, hid, acomm, arim);
    k_out<<<1024, 256>>>(hid, Wo, bo, outputs);
}

// round 4
// speedup vs baseline: 1.3645x; 1.3645x over previous
#include <cuda_runtime.h>
#include <cuda_bf16.h>
#include <cstdint>

#define B_ 128
#define S_ 512
#define I_ 128
#define H_ 128
#define M_ 8
#define KD_ 16
#define R_ 16
#define O_ 128

// output region offsets (floats), concatenated in reference return order
#define OFF_OUT   ((size_t)0)                 // [B,S,O]      8388608
#define OFF_HID   ((size_t)8388608)           // [S,B,M,H]   67108864
#define OFF_AIN   ((size_t)75497472)          // [S,B,M,H]   67108864
#define OFF_ACOMM ((size_t)142606336)         // [S,B,M,H]   67108864
#define OFF_ARIM  ((size_t)209715200)         // [S,B,M,M]    4194304

__device__ float g_P[(size_t)S_ * B_ * M_ * H_];   // precomputed input_part + biases
__device__ float g_Weff[M_ * I_ * H_];             // W_in @ Wp^T per mechanism

typedef unsigned long long ull;

__device__ __forceinline__ ull ffma2(ull a, ull b, ull c) {
    ull d;
    asm("fma.rn.f32x2 %0, %1, %2, %3;" : "=l"(d) : "l"(a), "l"(b), "l"(c));
    return d;
}
__device__ __forceinline__ ull pack2(float x, float y) {
    ull d; asm("mov.b64 %0, {%1, %2};" : "=l"(d) : "f"(x), "f"(y)); return d;
}
__device__ __forceinline__ float2 unpack2(ull v) {
    float2 r; asm("mov.b64 {%0, %1}, %2;" : "=f"(r.x), "=f"(r.y) : "l"(v)); return r;
}
__device__ __forceinline__ float tanh_fast(float x) {
    float e = __expf(2.0f * x);
    return 1.0f - 2.0f / (e + 1.0f);
}
__device__ __forceinline__ void cp16(void* s, const void* g) {
    unsigned ds = (unsigned)__cvta_generic_to_shared(s);
    asm volatile("cp.async.cg.shared.global [%0], [%1], 16;" :: "r"(ds), "l"(g));
}

// ---------------------------------------------------------------------------
// k_weff: Weff[m][i][o] = sum_h Win[m][i][h] * Wp[m][o][h].  grid (2,8), 256t
// ---------------------------------------------------------------------------
__global__ void k_weff(const float* __restrict__ Win, const float* __restrict__ Wp) {
    __shared__ float sA[64][36];
    __shared__ float sBt[32][132];
    int m = blockIdx.y;
    int i0 = blockIdx.x * 64;
    int tid = threadIdx.x;
    int ty = tid >> 5, tx = tid & 31;
    int w = tid >> 5, lane = tid & 31;

    float acc[8][4];
#pragma unroll
    for (int a = 0; a < 8; a++)
#pragma unroll
        for (int c = 0; c < 4; c++) acc[a][c] = 0.f;

    const float* A = Win + m * 16384;
    const float* Bm = Wp + m * 16384;

    for (int kc = 0; kc < 128; kc += 32) {
        {
            int row = tid >> 2, cs = (tid & 3) * 8;
            const float* ap = A + (i0 + row) * 128 + kc + cs;
            *(float4*)&sA[row][cs]     = *(const float4*)ap;
            *(float4*)&sA[row][cs + 4] = *(const float4*)(ap + 4);
        }
        {
            int og = lane >> 3, ii0 = (lane & 7) * 4;
#pragma unroll
            for (int it = 0; it < 4; it++) {
                int o = (w << 4) + og + (it << 2);
                float4 v = *(const float4*)(Bm + o * 128 + kc + ii0);
                sBt[ii0 + 0][o] = v.x; sBt[ii0 + 1][o] = v.y;
                sBt[ii0 + 2][o] = v.z; sBt[ii0 + 3][o] = v.w;
            }
        }
        __syncthreads();
#pragma unroll 8
        for (int kk = 0; kk < 32; kk++) {
            float4 wv = *(float4*)&sBt[kk][tx * 4];
#pragma unroll
            for (int rr = 0; rr < 8; rr++) {
                float av = sA[ty * 8 + rr][kk];
                acc[rr][0] += av * wv.x; acc[rr][1] += av * wv.y;
                acc[rr][2] += av * wv.z; acc[rr][3] += av * wv.w;
            }
        }
        __syncthreads();
    }
    float* dst = g_Weff + m * 16384;
#pragma unroll
    for (int rr = 0; rr < 8; rr++) {
        float4 v = make_float4(acc[rr][0], acc[rr][1], acc[rr][2], acc[rr][3]);
        *(float4*)&dst[(i0 + ty * 8 + rr) * 128 + tx * 4] = v;
    }
}

// ---------------------------------------------------------------------------
// k_pre: A_in[t,b,m,:] = x[b,t,:] @ Win[m];  P = x @ Weff[m] + bp+cb
// grid (1024, 8): 64 (t,b)-rows per block, m = blockIdx.y. 256 threads.
// f32x2 dual-accumulator inner loop.
// ---------------------------------------------------------------------------
__global__ __launch_bounds__(256) void k_pre(const float* __restrict__ x,
        const float* __restrict__ Win, const float* __restrict__ bp,
        const float* __restrict__ cb, float* __restrict__ ain) {
    __shared__ float sX[64][36];
    __shared__ float sW1[32][132];
    __shared__ float sW2[32][132];
    int m = blockIdx.y;
    int r0 = blockIdx.x * 64;
    int t = r0 >> 7, b0 = r0 & 127;
    int tid = threadIdx.x;
    int ty = tid >> 5, tx = tid & 31;

    ull acc1[8][2], acc2[8][2];
#pragma unroll
    for (int a = 0; a < 8; a++) {
        acc1[a][0] = 0; acc1[a][1] = 0; acc2[a][0] = 0; acc2[a][1] = 0;
    }

    const float* W1 = Win + m * 16384;
    const float* W2 = g_Weff + m * 16384;

    for (int kc = 0; kc < 128; kc += 32) {
        {
            int row = tid >> 2, cs = (tid & 3) * 8;
            const float* xp = x + ((size_t)(b0 + row) * 512 + t) * 128 + kc + cs;
            *(float4*)&sX[row][cs]     = *(const float4*)xp;
            *(float4*)&sX[row][cs + 4] = *(const float4*)(xp + 4);
        }
        {
            int i = tid >> 3, h0 = (tid & 7) * 16;
            const float* w1 = W1 + (kc + i) * 128 + h0;
            const float* w2 = W2 + (kc + i) * 128 + h0;
#pragma unroll
            for (int j = 0; j < 4; j++) {
                *(float4*)&sW1[i][h0 + 4 * j] = *(const float4*)(w1 + 4 * j);
                *(float4*)&sW2[i][h0 + 4 * j] = *(const float4*)(w2 + 4 * j);
            }
        }
        __syncthreads();
#pragma unroll 8
        for (int kk = 0; kk < 32; kk++) {
            ulonglong2 w1 = *(const ulonglong2*)&sW1[kk][tx * 4];
            ulonglong2 w2 = *(const ulonglong2*)&sW2[kk][tx * 4];
#pragma unroll
            for (int rr = 0; rr < 8; rr++) {
                float xv = sX[ty * 8 + rr][kk];
                ull xp = pack2(xv, xv);
                acc1[rr][0] = ffma2(xp, w1.x, acc1[rr][0]);
                acc1[rr][1] = ffma2(xp, w1.y, acc1[rr][1]);
                acc2[rr][0] = ffma2(xp, w2.x, acc2[rr][0]);
                acc2[rr][1] = ffma2(xp, w2.y, acc2[rr][1]);
            }
        }
        __syncthreads();
    }
    float4 bi = *(const float4*)&bp[m * 128 + tx * 4];
    float4 ci = *(const float4*)&cb[m * 128 + tx * 4];
    float4 bias = make_float4(bi.x + ci.x, bi.y + ci.y, bi.z + ci.z, bi.w + ci.w);
#pragma unroll
    for (int rr = 0; rr < 8; rr++) {
        size_t gr = r0 + ty * 8 + rr;
        size_t base = (gr * 8 + m) * 128 + tx * 4;
        float2 a0 = unpack2(acc1[rr][0]), a1 = unpack2(acc1[rr][1]);
        float2 p0 = unpack2(acc2[rr][0]), p1 = unpack2(acc2[rr][1]);
        *(float4*)&ain[base] = make_float4(a0.x, a0.y, a1.x, a1.y);
        *(float4*)&g_P[base] = make_float4(p0.x + bias.x, p0.y + bias.y,
                                           p1.x + bias.z, p1.y + bias.w);
    }
}

// ---------------------------------------------------------------------------
// k_rnn v2: persistent per-batch recurrence. 128 blocks, 256 threads.
//  - Q/K projection weights register-resident (64 f32x2 per lane)
//  - U padded (stride 17) -> conflict-free
//  - per-warp redundant 8x8 softmax -> only 2 __syncthreads per step
// ---------------------------------------------------------------------------
struct Smem3 {
    float U[M_][H_][17];          // 69632 B, padded
    float V[M_][R_][H_];          // 65536 B
    float diag[M_][H_];           // 4 KB
    float Hst[M_][H_];            // 4 KB
    float Hin[M_][H_];            // 4 KB
    float VcT[M_][H_];            // 4 KB
    float P[2][M_ * H_];          // 8 KB
    float KQ[M_][33];             // padded: bank (m+c)%32
};

__global__ __launch_bounds__(256) void k_rnn(
        const float* __restrict__ U, const float* __restrict__ V,
        const float* __restrict__ WQ, const float* __restrict__ WK,
        const float* __restrict__ WV,
        float* __restrict__ hid, float* __restrict__ acomm,
        float* __restrict__ arim) {
    extern __shared__ char raw[];
    Smem3& sm = *reinterpret_cast<Smem3*>(raw);
    int tid = threadIdx.x;
    int b = blockIdx.x;
    int w = tid >> 5, lane = tid & 31;
    const int m = w;
    const int r = lane & 15, hf = lane >> 4;

    // -------- init --------
    // U with pad-17
    for (int e = tid; e < M_ * H_ * R_; e += 256) {
        int mm = e >> 11, h = (e >> 4) & 127, rr = e & 15;
        sm.U[mm][h][rr] = U[e];
    }
    for (int i = tid * 4; i < M_ * R_ * H_; i += 256 * 4)
        *(float4*)((float*)sm.V + i) = *(const float4*)(V + i);
    for (int e = tid; e < M_ * H_; e += 256) {
        int mm = e >> 7, h = e & 127;
        sm.diag[mm][h] = WV[((size_t)mm * H_ + h) * H_ + h];
        sm.Hst[mm][h] = 0.f;
    }
    // register-resident projection column: lane c<16 -> W_K col c, c>=16 -> W_Q col c-16
    ull wreg[64];
    {
        const float* src = (lane < 16) ? (WK + m * H_ * KD_ + lane)
                                       : (WQ + m * H_ * KD_ + (lane - 16));
#pragma unroll
        for (int hp = 0; hp < 64; hp++)
            wreg[hp] = pack2(src[(2 * hp) * KD_], src[(2 * hp + 1) * KD_]);
    }
    const float* Pb = g_P + (size_t)b * 1024;
    cp16(&sm.P[0][tid * 4], Pb + tid * 4);
    asm volatile("cp.async.commit_group;");
    __syncthreads();

    for (int t = 0; t < S_; t++) {
        if (t + 1 < S_) {
            cp16(&sm.P[(t + 1) & 1][tid * 4],
                 Pb + (size_t)(t + 1) * (B_ * 1024) + tid * 4);
            asm volatile("cp.async.commit_group;");
            asm volatile("cp.async.wait_group 1;");
        } else {
            asm volatile("cp.async.wait_group 0;");
        }
        __syncwarp();

        // ---- phase A: rec = (H @ U) @ V ; Hin = tanh(P+rec) ; VcT = Hin*diag
        float4 hin;
        {
            const float* Uc = &sm.U[m][hf * 64][r];
            const float* Hc = &sm.Hst[m][hf * 64];
            float p0 = 0, p1 = 0, p2 = 0, p3 = 0;
#pragma unroll
            for (int hh = 0; hh < 64; hh += 4) {
                p0 += Hc[hh + 0] * Uc[(hh + 0) * 17];
                p1 += Hc[hh + 1] * Uc[(hh + 1) * 17];
                p2 += Hc[hh + 2] * Uc[(hh + 2) * 17];
                p3 += Hc[hh + 3] * Uc[(hh + 3) * 17];
            }
            float partial = (p0 + p1) + (p2 + p3);
            partial += __shfl_xor_sync(0xffffffffu, partial, 16);
            ull ax = 0, ay = 0;
#pragma unroll
            for (int rr = 0; rr < 16; rr++) {
                float tr = __shfl_sync(0xffffffffu, partial, rr);
                ull tp = pack2(tr, tr);
                ulonglong2 v = *(const ulonglong2*)&sm.V[m][rr][lane * 4];
                ax = ffma2(tp, v.x, ax);
                ay = ffma2(tp, v.y, ay);
            }
            float2 a01 = unpack2(ax), a23 = unpack2(ay);
            float4 pv = *(const float4*)&sm.P[t & 1][tid * 4];
            hin.x = tanh_fast(pv.x + a01.x);
            hin.y = tanh_fast(pv.y + a01.y);
            hin.z = tanh_fast(pv.z + a23.x);
            hin.w = tanh_fast(pv.w + a23.y);
            *(float4*)&sm.Hin[m][lane * 4] = hin;
            float4 dg = *(const float4*)&sm.diag[m][lane * 4];
            *(float4*)&sm.VcT[m][lane * 4] =
                make_float4(hin.x * dg.x, hin.y * dg.y, hin.z * dg.z, hin.w * dg.w);
        }

        // ---- phase B: K/Q projection, weights in registers, Hin broadcast
        {
            ull acc0 = 0, acc1 = 0;
            const ulonglong2* hb = (const ulonglong2*)&sm.Hin[m][0];
#pragma unroll
            for (int i = 0; i < 32; i++) {
                ulonglong2 h = hb[i];
                acc0 = ffma2(h.x, wreg[2 * i], acc0);
                acc1 = ffma2(h.y, wreg[2 * i + 1], acc1);
            }
            float2 s0 = unpack2(acc0), s1 = unpack2(acc1);
            sm.KQ[m][lane] = (s0.x + s0.y) + (s1.x + s1.y);
        }
        __syncthreads();

        // ---- phase C: per-warp redundant 8x8 attention + comm + update
        {
            int mq = lane >> 2, g = lane & 3;   // lane owns logits[mq][2g],[2g+1]
            float L0 = 0.f, L1 = 0.f;
#pragma unroll
            for (int k = 0; k < 16; k++) {
                float q = sm.KQ[mq][16 + k];
                L0 += q * sm.KQ[2 * g][k];
                L1 += q * sm.KQ[2 * g + 1][k];
            }
            L0 *= 0.25f; L1 *= 0.25f;
            float mx = fmaxf(L0, L1);
            mx = fmaxf(mx, __shfl_xor_sync(0xffffffffu, mx, 1));
            mx = fmaxf(mx, __shfl_xor_sync(0xffffffffu, mx, 2));
            float e0 = __expf(L0 - mx), e1 = __expf(L1 - mx);
            float s = e0 + e1;
            s += __shfl_xor_sync(0xffffffffu, s, 1);
            s += __shfl_xor_sync(0xffffffffu, s, 2);
            float inv = 1.0f / s;
            float a0 = e0 * inv, a1 = e1 * inv;  // attn[mq][2g], attn[mq][2g+1]

            if (w == 0)
                *(float2*)&arim[((size_t)t * B_ + b) * 64 + lane * 2] =
                    make_float2(a0, a1);

            // A_comm[n=w][h] = sum_mm attn[mm][w] * VcT[mm][h]
            int n = w;
            float av = (n & 1) ? a1 : a0;
            ull cx = 0, cy = 0;
#pragma unroll
            for (int mm = 0; mm < 8; mm++) {
                float a = __shfl_sync(0xffffffffu, av, mm * 4 + (n >> 1));
                ull ap = pack2(a, a);
                ulonglong2 vc = *(const ulonglong2*)&sm.VcT[mm][lane * 4];
                cx = ffma2(ap, vc.x, cx);
                cy = ffma2(ap, vc.y, cy);
            }
            float2 c01 = unpack2(cx), c23 = unpack2(cy);
            float4 ac = make_float4(c01.x, c01.y, c23.x, c23.y);
            float4 hn = make_float4(hin.x + ac.x, hin.y + ac.y,
                                    hin.z + ac.z, hin.w + ac.w);
            *(float4*)&sm.Hst[n][lane * 4] = hn;
            size_t base = (((size_t)t * B_ + b) * M_ + n) * H_ + lane * 4;
            *(float4*)&hid[base] = hn;
            *(float4*)&acomm[base] = ac;
        }
        __syncthreads();
    }
}

// ---------------------------------------------------------------------------
// k_out: out[b,t,o] = hid[t,b,:,:] (flat 1024) @ Wo^T + bo. grid 1024, 256t.
// f32x2 inner loop.
// ---------------------------------------------------------------------------
__global__ __launch_bounds__(256) void k_out(const float* __restrict__ hid,
        const float* __restrict__ Wo, const float* __restrict__ bo,
        float* __restrict__ outp) {
    __shared__ float sA[64][36];
    __shared__ float sBt[32][132];
    int r0 = blockIdx.x * 64;
    int tid = threadIdx.x;
    int ty = tid >> 5, tx = tid & 31;
    int w = tid >> 5, lane = tid & 31;

    ull acc[8][2];
#pragma unroll
    for (int a = 0; a < 8; a++) { acc[a][0] = 0; acc[a][1] = 0; }

    for (int kc = 0; kc < 1024; kc += 32) {
        {
            int row = tid >> 2, cs = (tid & 3) * 8;
            const float* ap = hid + (size_t)(r0 + row) * 1024 + kc + cs;
            *(float4*)&sA[row][cs]     = *(const float4*)ap;
            *(float4*)&sA[row][cs + 4] = *(const float4*)(ap + 4);
        }
        {
            int og = lane >> 3, ii0 = (lane & 7) * 4;
#pragma unroll
            for (int it = 0; it < 4; it++) {
                int o = (w << 4) + og + (it << 2);
                float4 v = *(const float4*)(Wo + (size_t)o * 1024 + kc + ii0);
                sBt[ii0 + 0][o] = v.x; sBt[ii0 + 1][o] = v.y;
                sBt[ii0 + 2][o] = v.z; sBt[ii0 + 3][o] = v.w;
            }
        }
        __syncthreads();
#pragma unroll 8
        for (int kk = 0; kk < 32; kk++) {
            ulonglong2 wv = *(const ulonglong2*)&sBt[kk][tx * 4];
#pragma unroll
            for (int rr = 0; rr < 8; rr++) {
                float av = sA[ty * 8 + rr][kk];
                ull ap = pack2(av, av);
                acc[rr][0] = ffma2(ap, wv.x, acc[rr][0]);
                acc[rr][1] = ffma2(ap, wv.y, acc[rr][1]);
            }
        }
        __syncthreads();
    }
    float4 b4 = *(const float4*)&bo[tx * 4];
#pragma unroll
    for (int rr = 0; rr < 8; rr++) {
        int rg = r0 + ty * 8 + rr;
        int t = rg >> 7, b = rg & 127;
        float2 v0 = unpack2(acc[rr][0]), v1 = unpack2(acc[rr][1]);
        float4 v = make_float4(v0.x + b4.x, v0.y + b4.y, v1.x + b4.z, v1.y + b4.w);
        *(float4*)&outp[((size_t)b * 512 + t) * 128 + tx * 4] = v;
    }
}

// ---------------------------------------------------------------------------
extern "C" void kernel_launch(void* const* d_in, const int* in_sizes, int n_in,
                              void* d_out, int out_size) {
    const float* x    = (const float*)d_in[0];
    const float* Wp   = (const float*)d_in[1];
    const float* bp   = (const float*)d_in[2];
    const float* U    = (const float*)d_in[3];
    const float* V    = (const float*)d_in[4];
    const float* cb   = (const float*)d_in[5];
    const float* Win  = (const float*)d_in[6];
    const float* WQ   = (const float*)d_in[7];
    const float* WK   = (const float*)d_in[8];
    const float* WV   = (const float*)d_in[9];
    const float* Wo   = (const float*)d_in[10];
    const float* bo   = (const float*)d_in[11];

    float* out = (float*)d_out;
    float* outputs = out + OFF_OUT;
    float* hid     = out + OFF_HID;
    float* ain     = out + OFF_AIN;
    float* acomm   = out + OFF_ACOMM;
    float* arim    = out + OFF_ARIM;

    cudaFuncSetAttribute(k_rnn, cudaFuncAttributeMaxDynamicSharedMemorySize,
                         (int)sizeof(Smem3));

    k_weff<<<dim3(2, 8), 256>>>(Win, Wp);
    k_pre<<<dim3(1024, 8), 256>>>(x, Win, bp, cb, ain);
    k_rnn<<<128, 256, sizeof(Smem3)>>>(U, V, WQ, WK, WV, hid, acomm, arim);
    k_out<<<1024, 256>>>(hid, Wo, bo, outputs);
}

// round 7
// speedup vs baseline: 1.5723x; 1.1523x over previous
#include <cuda_runtime.h>
#include <cuda_bf16.h>
#include <cstdint>

#define B_ 128
#define S_ 512
#define I_ 128
#define H_ 128
#define M_ 8
#define KD_ 16
#define R_ 16
#define O_ 128

// output region offsets (floats), concatenated in reference return order
#define OFF_OUT   ((size_t)0)                 // [B,S,O]      8388608
#define OFF_HID   ((size_t)8388608)           // [S,B,M,H]   67108864
#define OFF_AIN   ((size_t)75497472)          // [S,B,M,H]   67108864
#define OFF_ACOMM ((size_t)142606336)         // [S,B,M,H]   67108864
#define OFF_ARIM  ((size_t)209715200)         // [S,B,M,M]    4194304

__device__ float g_P[(size_t)S_ * B_ * M_ * H_];   // precomputed input_part + biases
__device__ float g_Weff[M_ * I_ * H_];             // W_in @ Wp^T per mechanism

typedef unsigned long long ull;

__device__ __forceinline__ ull ffma2(ull a, ull b, ull c) {
    ull d;
    asm("fma.rn.f32x2 %0, %1, %2, %3;" : "=l"(d) : "l"(a), "l"(b), "l"(c));
    return d;
}
__device__ __forceinline__ ull pack2(float x, float y) {
    ull d; asm("mov.b64 %0, {%1, %2};" : "=l"(d) : "f"(x), "f"(y)); return d;
}
__device__ __forceinline__ float2 unpack2(ull v) {
    float2 r; asm("mov.b64 {%0, %1}, %2;" : "=f"(r.x), "=f"(r.y) : "l"(v)); return r;
}
__device__ __forceinline__ float tanh_fast(float x) {
    float e = __expf(2.0f * x);
    return 1.0f - 2.0f / (e + 1.0f);
}
__device__ __forceinline__ void cp16(void* s, const void* g) {
    unsigned ds = (unsigned)__cvta_generic_to_shared(s);
    asm volatile("cp.async.cg.shared.global [%0], [%1], 16;" :: "r"(ds), "l"(g));
}

// ---------------------------------------------------------------------------
// k_weff: Weff[m][i][o] = sum_h Win[m][i][h] * Wp[m][o][h].  grid (2,8), 256t
// ---------------------------------------------------------------------------
__global__ void k_weff(const float* __restrict__ Win, const float* __restrict__ Wp) {
    __shared__ float sA[64][36];
    __shared__ float sBt[32][132];
    int m = blockIdx.y;
    int i0 = blockIdx.x * 64;
    int tid = threadIdx.x;
    int ty = tid >> 5, tx = tid & 31;
    int w = tid >> 5, lane = tid & 31;

    float acc[8][4];
#pragma unroll
    for (int a = 0; a < 8; a++)
#pragma unroll
        for (int c = 0; c < 4; c++) acc[a][c] = 0.f;

    const float* A = Win + m * 16384;
    const float* Bm = Wp + m * 16384;

    for (int kc = 0; kc < 128; kc += 32) {
        {
            int row = tid >> 2, cs = (tid & 3) * 8;
            const float* ap = A + (i0 + row) * 128 + kc + cs;
            *(float4*)&sA[row][cs]     = *(const float4*)ap;
            *(float4*)&sA[row][cs + 4] = *(const float4*)(ap + 4);
        }
        {
            int og = lane >> 3, ii0 = (lane & 7) * 4;
#pragma unroll
            for (int it = 0; it < 4; it++) {
                int o = (w << 4) + og + (it << 2);
                float4 v = *(const float4*)(Bm + o * 128 + kc + ii0);
                sBt[ii0 + 0][o] = v.x; sBt[ii0 + 1][o] = v.y;
                sBt[ii0 + 2][o] = v.z; sBt[ii0 + 3][o] = v.w;
            }
        }
        __syncthreads();
#pragma unroll 8
        for (int kk = 0; kk < 32; kk++) {
            float4 wv = *(float4*)&sBt[kk][tx * 4];
#pragma unroll
            for (int rr = 0; rr < 8; rr++) {
                float av = sA[ty * 8 + rr][kk];
                acc[rr][0] += av * wv.x; acc[rr][1] += av * wv.y;
                acc[rr][2] += av * wv.z; acc[rr][3] += av * wv.w;
            }
        }
        __syncthreads();
    }
    float* dst = g_Weff + m * 16384;
#pragma unroll
    for (int rr = 0; rr < 8; rr++) {
        float4 v = make_float4(acc[rr][0], acc[rr][1], acc[rr][2], acc[rr][3]);
        *(float4*)&dst[(i0 + ty * 8 + rr) * 128 + tx * 4] = v;
    }
}

// ---------------------------------------------------------------------------
// k_pre v3: one block = 64 (t,b)-rows, ALL 8 mechanisms (x tile loaded once).
// grid 1024, 256 threads, dynamic smem.
// ---------------------------------------------------------------------------
#define PRE_SMEM ((64 * 132 + 2 * 32 * 132) * 4)

__global__ __launch_bounds__(256) void k_pre(const float* __restrict__ x,
        const float* __restrict__ Win, const float* __restrict__ bp,
        const float* __restrict__ cb, float* __restrict__ ain) {
    extern __shared__ float ps[];
    float (*sX)[132]  = (float(*)[132])ps;                // [64][132]
    float (*sW1)[132] = (float(*)[132])(ps + 64 * 132);   // [32][132]
    float (*sW2)[132] = (float(*)[132])(ps + 96 * 132);   // [32][132]

    int r0 = blockIdx.x * 64;
    int t = r0 >> 7, b0 = r0 & 127;
    int tid = threadIdx.x;
    int ty = tid >> 5, tx = tid & 31;

    // load X tile once: 64 rows x 128
    {
        int row = tid >> 2, c0 = (tid & 3) * 32;
        const float* xp = x + ((size_t)(b0 + row) * 512 + t) * 128 + c0;
#pragma unroll
        for (int j = 0; j < 8; j++)
            *(float4*)&sX[row][c0 + 4 * j] = *(const float4*)(xp + 4 * j);
    }
    __syncthreads();

    for (int m = 0; m < 8; m++) {
        const float* W1 = Win + m * 16384;
        const float* W2 = g_Weff + m * 16384;

        ull acc1[8][2], acc2[8][2];
#pragma unroll
        for (int a = 0; a < 8; a++) {
            acc1[a][0] = 0; acc1[a][1] = 0; acc2[a][0] = 0; acc2[a][1] = 0;
        }

        for (int kc = 0; kc < 128; kc += 32) {
            {
                int i = tid >> 3, h0 = (tid & 7) * 16;
                const float* w1 = W1 + (kc + i) * 128 + h0;
                const float* w2 = W2 + (kc + i) * 128 + h0;
#pragma unroll
                for (int j = 0; j < 4; j++) {
                    *(float4*)&sW1[i][h0 + 4 * j] = *(const float4*)(w1 + 4 * j);
                    *(float4*)&sW2[i][h0 + 4 * j] = *(const float4*)(w2 + 4 * j);
                }
            }
            __syncthreads();
#pragma unroll 8
            for (int kk = 0; kk < 32; kk++) {
                ulonglong2 w1 = *(const ulonglong2*)&sW1[kk][tx * 4];
                ulonglong2 w2 = *(const ulonglong2*)&sW2[kk][tx * 4];
#pragma unroll
                for (int rr = 0; rr < 8; rr++) {
                    float xv = sX[ty * 8 + rr][kc + kk];
                    ull xp2 = pack2(xv, xv);
                    acc1[rr][0] = ffma2(xp2, w1.x, acc1[rr][0]);
                    acc1[rr][1] = ffma2(xp2, w1.y, acc1[rr][1]);
                    acc2[rr][0] = ffma2(xp2, w2.x, acc2[rr][0]);
                    acc2[rr][1] = ffma2(xp2, w2.y, acc2[rr][1]);
                }
            }
            __syncthreads();
        }
        float4 bi = *(const float4*)&bp[m * 128 + tx * 4];
        float4 ci = *(const float4*)&cb[m * 128 + tx * 4];
        float4 bias = make_float4(bi.x + ci.x, bi.y + ci.y, bi.z + ci.z, bi.w + ci.w);
#pragma unroll
        for (int rr = 0; rr < 8; rr++) {
            size_t gr = r0 + ty * 8 + rr;
            size_t base = (gr * 8 + m) * 128 + tx * 4;
            float2 a0 = unpack2(acc1[rr][0]), a1 = unpack2(acc1[rr][1]);
            float2 p0 = unpack2(acc2[rr][0]), p1 = unpack2(acc2[rr][1]);
            *(float4*)&ain[base] = make_float4(a0.x, a0.y, a1.x, a1.y);
            *(float4*)&g_P[base] = make_float4(p0.x + bias.x, p0.y + bias.y,
                                               p1.x + bias.z, p1.y + bias.w);
        }
    }
}

// ---------------------------------------------------------------------------
// k_rnn v3: 128 blocks, 256 threads. 1 __syncthreads/step.
//  - U repacked lane-indexed (conflict-free LDS.128)
//  - VcT/KQ double-buffered by parity
//  - 4-deep cp.async P ring (each thread owns its 16B; no barrier needed)
// ---------------------------------------------------------------------------
struct Smem3 {
    float4 Ut4[M_][16][32];       // 65536 B: Ut4[m][i][lane].j = U[m][hf*64+4i+j][r]
    float V[M_][R_][H_];          // 65536 B
    float diag[M_][H_];           // 4 KB
    float Hst[M_][H_];            // 4 KB
    float Hin[M_][H_];            // 4 KB
    float VcT[2][M_][H_];         // 8 KB (parity)
    float P[4][M_ * H_];          // 16 KB ring
    float KQ[2][M_][33];          // parity
};

__global__ __launch_bounds__(256) void k_rnn(
        const float* __restrict__ U, const float* __restrict__ V,
        const float* __restrict__ WQ, const float* __restrict__ WK,
        const float* __restrict__ WV,
        float* __restrict__ hid, float* __restrict__ acomm,
        float* __restrict__ arim) {
    extern __shared__ char raw[];
    Smem3& sm = *reinterpret_cast<Smem3*>(raw);
    int tid = threadIdx.x;
    int b = blockIdx.x;
    int w = tid >> 5, lane = tid & 31;
    const int m = w;
    const int r = lane & 15, hf = lane >> 4;

    // -------- init --------
    // U repack: Ut4[m][i][lane].j = U[m][hf*64 + 4i + j][r]
    {
#pragma unroll
        for (int i = 0; i < 16; i++) {
            int hb = hf * 64 + i * 4;
            float4 v;
            v.x = U[((size_t)m * 128 + hb + 0) * 16 + r];
            v.y = U[((size_t)m * 128 + hb + 1) * 16 + r];
            v.z = U[((size_t)m * 128 + hb + 2) * 16 + r];
            v.w = U[((size_t)m * 128 + hb + 3) * 16 + r];
            sm.Ut4[m][i][lane] = v;
        }
    }
    for (int i = tid * 4; i < M_ * R_ * H_; i += 256 * 4)
        *(float4*)((float*)sm.V + i) = *(const float4*)(V + i);
    for (int e = tid; e < M_ * H_; e += 256) {
        int mm = e >> 7, h = e & 127;
        sm.diag[mm][h] = WV[((size_t)mm * H_ + h) * H_ + h];
        sm.Hst[mm][h] = 0.f;
    }
    // register-resident projection column: lane c<16 -> W_K col c, c>=16 -> W_Q col c-16
    ull wreg[64];
    {
        const float* src = (lane < 16) ? (WK + m * H_ * KD_ + lane)
                                       : (WQ + m * H_ * KD_ + (lane - 16));
#pragma unroll
        for (int hp = 0; hp < 64; hp++)
            wreg[hp] = pack2(src[(2 * hp) * KD_], src[(2 * hp + 1) * KD_]);
    }
    const float* Pb = g_P + (size_t)b * 1024;
    // prologue: prefetch t = 0,1,2
#pragma unroll
    for (int pt = 0; pt < 3; pt++) {
        cp16(&sm.P[pt][tid * 4], Pb + (size_t)pt * (B_ * 1024) + tid * 4);
        asm volatile("cp.async.commit_group;");
    }
    __syncthreads();

    for (int t = 0; t < S_; t++) {
        const int p = t & 1;
        if (t + 3 < S_)
            cp16(&sm.P[(t + 3) & 3][tid * 4],
                 Pb + (size_t)(t + 3) * (B_ * 1024) + tid * 4);
        asm volatile("cp.async.commit_group;");
        asm volatile("cp.async.wait_group 3;");

        // ---- phase A: rec = (H @ U) @ V ; Hin = tanh(P+rec) ; VcT = Hin*diag
        float4 hin;
        {
            const float4* Hc = (const float4*)&sm.Hst[m][hf * 64];
            ull s0 = 0, s1 = 0;
#pragma unroll
            for (int i = 0; i < 16; i++) {
                float4 u = sm.Ut4[m][i][lane];
                float4 h = Hc[i];
                s0 = ffma2(pack2(h.x, h.y), pack2(u.x, u.y), s0);
                s1 = ffma2(pack2(h.z, h.w), pack2(u.z, u.w), s1);
            }
            float2 t0 = unpack2(s0), t1 = unpack2(s1);
            float partial = (t0.x + t0.y) + (t1.x + t1.y);
            partial += __shfl_xor_sync(0xffffffffu, partial, 16);
            ull ax = 0, ay = 0;
#pragma unroll
            for (int rr = 0; rr < 16; rr++) {
                float tr = __shfl_sync(0xffffffffu, partial, rr);
                ull tp = pack2(tr, tr);
                ulonglong2 v = *(const ulonglong2*)&sm.V[m][rr][lane * 4];
                ax = ffma2(tp, v.x, ax);
                ay = ffma2(tp, v.y, ay);
            }
            float2 a01 = unpack2(ax), a23 = unpack2(ay);
            float4 pv = *(const float4*)&sm.P[t & 3][tid * 4];
            hin.x = tanh_fast(pv.x + a01.x);
            hin.y = tanh_fast(pv.y + a01.y);
            hin.z = tanh_fast(pv.z + a23.x);
            hin.w = tanh_fast(pv.w + a23.y);
            *(float4*)&sm.Hin[m][lane * 4] = hin;
            float4 dg = *(const float4*)&sm.diag[m][lane * 4];
            *(float4*)&sm.VcT[p][m][lane * 4] =
                make_float4(hin.x * dg.x, hin.y * dg.y, hin.z * dg.z, hin.w * dg.w);
        }
        __syncwarp();

        // ---- phase B: K/Q projection, weights in registers, Hin broadcast
        {
            ull acc0 = 0, acc1 = 0;
            const ulonglong2* hb = (const ulonglong2*)&sm.Hin[m][0];
#pragma unroll
            for (int i = 0; i < 32; i++) {
                ulonglong2 h = hb[i];
                acc0 = ffma2(h.x, wreg[2 * i], acc0);
                acc1 = ffma2(h.y, wreg[2 * i + 1], acc1);
            }
            float2 s0 = unpack2(acc0), s1 = unpack2(acc1);
            sm.KQ[p][m][lane] = (s0.x + s0.y) + (s1.x + s1.y);
        }
        __syncthreads();

        // ---- phase C: per-warp redundant 8x8 attention + comm + update
        {
            int mq = lane >> 2, g = lane & 3;   // lane owns logits[mq][2g],[2g+1]
            float L0 = 0.f, L1 = 0.f;
#pragma unroll
            for (int k = 0; k < 16; k++) {
                float q = sm.KQ[p][mq][16 + k];
                L0 += q * sm.KQ[p][2 * g][k];
                L1 += q * sm.KQ[p][2 * g + 1][k];
            }
            L0 *= 0.25f; L1 *= 0.25f;
            float mx = fmaxf(L0, L1);
            mx = fmaxf(mx, __shfl_xor_sync(0xffffffffu, mx, 1));
            mx = fmaxf(mx, __shfl_xor_sync(0xffffffffu, mx, 2));
            float e0 = __expf(L0 - mx), e1 = __expf(L1 - mx);
            float s = e0 + e1;
            s += __shfl_xor_sync(0xffffffffu, s, 1);
            s += __shfl_xor_sync(0xffffffffu, s, 2);
            float inv = 1.0f / s;
            float a0 = e0 * inv, a1 = e1 * inv;  // attn[mq][2g], attn[mq][2g+1]

            if (w == 0)
                *(float2*)&arim[((size_t)t * B_ + b) * 64 + lane * 2] =
                    make_float2(a0, a1);

            // A_comm[n=w][h] = sum_mm attn[mm][w] * VcT[mm][h]
            int n = w;
            float av = (n & 1) ? a1 : a0;
            ull cx = 0, cy = 0;
#pragma unroll
            for (int mm = 0; mm < 8; mm++) {
                float a = __shfl_sync(0xffffffffu, av, mm * 4 + (n >> 1));
                ull ap = pack2(a, a);
                ulonglong2 vc = *(const ulonglong2*)&sm.VcT[p][mm][lane * 4];
                cx = ffma2(ap, vc.x, cx);
                cy = ffma2(ap, vc.y, cy);
            }
            float2 c01 = unpack2(cx), c23 = unpack2(cy);
            float4 ac = make_float4(c01.x, c01.y, c23.x, c23.y);
            float4 hn = make_float4(hin.x + ac.x, hin.y + ac.y,
                                    hin.z + ac.z, hin.w + ac.w);
            *(float4*)&sm.Hst[n][lane * 4] = hn;
            size_t base = (((size_t)t * B_ + b) * M_ + n) * H_ + lane * 4;
            *(float4*)&hid[base] = hn;
            *(float4*)&acomm[base] = ac;
        }
        __syncwarp();   // Hst cross-lane visibility for next step's phase A
    }
}

// ---------------------------------------------------------------------------
// k_out v3: 128x128 tile, BK=16, register-prefetch double buffering, f32x2.
// grid 512, 256 threads.
// ---------------------------------------------------------------------------
__global__ __launch_bounds__(256) void k_out(const float* __restrict__ hid,
        const float* __restrict__ Wo, const float* __restrict__ bo,
        float* __restrict__ outp) {
    __shared__ float sAT[16][132];   // [k][row]
    __shared__ float sB[16][132];    // [k][o]
    int r0 = blockIdx.x * 128;
    int tid = threadIdx.x;
    int tx = tid & 15, ty = tid >> 4;

    int lrow = tid >> 1;            // 0..127
    int lkq  = (tid & 1) * 8;       // 0 or 8
    const float* aptr = hid + (size_t)(r0 + lrow) * 1024 + lkq;
    const float* bptr = Wo + (size_t)lrow * 1024 + lkq;

    ull acc[8][4];
#pragma unroll
    for (int a = 0; a < 8; a++)
#pragma unroll
        for (int c = 0; c < 4; c++) acc[a][c] = 0ull;

    float4 ra0 = *(const float4*)aptr;
    float4 ra1 = *(const float4*)(aptr + 4);
    float4 rb0 = *(const float4*)bptr;
    float4 rb1 = *(const float4*)(bptr + 4);

    for (int kc = 0; kc < 1024; kc += 16) {
        sAT[lkq + 0][lrow] = ra0.x; sAT[lkq + 1][lrow] = ra0.y;
        sAT[lkq + 2][lrow] = ra0.z; sAT[lkq + 3][lrow] = ra0.w;
        sAT[lkq + 4][lrow] = ra1.x; sAT[lkq + 5][lrow] = ra1.y;
        sAT[lkq + 6][lrow] = ra1.z; sAT[lkq + 7][lrow] = ra1.w;
        sB[lkq + 0][lrow] = rb0.x; sB[lkq + 1][lrow] = rb0.y;
        sB[lkq + 2][lrow] = rb0.z; sB[lkq + 3][lrow] = rb0.w;
        sB[lkq + 4][lrow] = rb1.x; sB[lkq + 5][lrow] = rb1.y;
        sB[lkq + 6][lrow] = rb1.z; sB[lkq + 7][lrow] = rb1.w;
        __syncthreads();
        if (kc + 16 < 1024) {
            aptr += 16; bptr += 16;
            ra0 = *(const float4*)aptr; ra1 = *(const float4*)(aptr + 4);
            rb0 = *(const float4*)bptr; rb1 = *(const float4*)(bptr + 4);
        }
#pragma unroll
        for (int k = 0; k < 16; k++) {
            float4 av0 = *(const float4*)&sAT[k][ty * 8];
            float4 av1 = *(const float4*)&sAT[k][ty * 8 + 4];
            float4 bv0 = *(const float4*)&sB[k][tx * 4];
            float4 bv1 = *(const float4*)&sB[k][64 + tx * 4];
            ull bb0 = pack2(bv0.x, bv0.y), bb1 = pack2(bv0.z, bv0.w);
            ull bb2 = pack2(bv1.x, bv1.y), bb3 = pack2(bv1.z, bv1.w);
            float av[8] = {av0.x, av0.y, av0.z, av0.w, av1.x, av1.y, av1.z, av1.w};
#pragma unroll
            for (int rr = 0; rr < 8; rr++) {
                ull ap = pack2(av[rr], av[rr]);
                acc[rr][0] = ffma2(ap, bb0, acc[rr][0]);
                acc[rr][1] = ffma2(ap, bb1, acc[rr][1]);
                acc[rr][2] = ffma2(ap, bb2, acc[rr][2]);
                acc[rr][3] = ffma2(ap, bb3, acc[rr][3]);
            }
        }
        __syncthreads();
    }
    float4 b4a = *(const float4*)&bo[tx * 4];
    float4 b4b = *(const float4*)&bo[64 + tx * 4];
#pragma unroll
    for (int rr = 0; rr < 8; rr++) {
        int rg = r0 + ty * 8 + rr;
        int t = rg >> 7, b = rg & 127;
        float2 v0 = unpack2(acc[rr][0]), v1 = unpack2(acc[rr][1]);
        float2 v2 = unpack2(acc[rr][2]), v3 = unpack2(acc[rr][3]);
        float* orow = outp + ((size_t)b * 512 + t) * 128;
        *(float4*)&orow[tx * 4] =
            make_float4(v0.x + b4a.x, v0.y + b4a.y, v1.x + b4a.z, v1.y + b4a.w);
        *(float4*)&orow[64 + tx * 4] =
            make_float4(v2.x + b4b.x, v2.y + b4b.y, v3.x + b4b.z, v3.y + b4b.w);
    }
}

// ---------------------------------------------------------------------------
extern "C" void kernel_launch(void* const* d_in, const int* in_sizes, int n_in,
                              void* d_out, int out_size) {
    const float* x    = (const float*)d_in[0];
    const float* Wp   = (const float*)d_in[1];
    const float* bp   = (const float*)d_in[2];
    const float* U    = (const float*)d_in[3];
    const float* V    = (const float*)d_in[4];
    const float* cb   = (const float*)d_in[5];
    const float* Win  = (const float*)d_in[6];
    const float* WQ   = (const float*)d_in[7];
    const float* WK   = (const float*)d_in[8];
    const float* WV   = (const float*)d_in[9];
    const float* Wo   = (const float*)d_in[10];
    const float* bo   = (const float*)d_in[11];

    float* out = (float*)d_out;
    float* outputs = out + OFF_OUT;
    float* hid     = out + OFF_HID;
    float* ain     = out + OFF_AIN;
    float* acomm   = out + OFF_ACOMM;
    float* arim    = out + OFF_ARIM;

    cudaFuncSetAttribute(k_rnn, cudaFuncAttributeMaxDynamicSharedMemorySize,
                         (int)sizeof(Smem3));
    cudaFuncSetAttribute(k_pre, cudaFuncAttributeMaxDynamicSharedMemorySize,
                         PRE_SMEM);

    k_weff<<<dim3(2, 8), 256>>>(Win, Wp);
    k_pre<<<1024, 256, PRE_SMEM>>>(x, Win, bp, cb, ain);
    k_rnn<<<128, 256, sizeof(Smem3)>>>(U, V, WQ, WK, WV, hid, acomm, arim);
    k_out<<<512, 256>>>(hid, Wo, bo, outputs);
}